// round 3
// baseline (speedup 1.0000x reference)
#include <cuda_runtime.h>
#include <cuda_fp16.h>

#define NMAX 50000
#define EMAX 800000
#define GMAXC 64
#define BN_EPS 1e-5f

typedef unsigned long long u64;

// ---- f32x2 packed-FMA helpers (FFMA2: PTX-only path on sm_103a) ----
__device__ __forceinline__ u64 pk2(float lo, float hi) {
    u64 r; asm("mov.b64 %0, {%1,%2};" : "=l"(r) : "f"(lo), "f"(hi)); return r;
}
__device__ __forceinline__ void fma2(u64& d, u64 a, u64 b) {
    asm("fma.rn.f32x2 %0, %1, %2, %3;" : "=l"(d) : "l"(a), "l"(b), "l"(d));
}
__device__ __forceinline__ float2 upk(u64 v) {
    float lo, hi; asm("mov.b64 {%0,%1}, %2;" : "=f"(lo), "=f"(hi) : "l"(v));
    return make_float2(lo, hi);
}

// ---------- static device scratch (no allocation allowed) ----------
__device__ uint4  g_P4[(size_t)NMAX * 160];    // P: [n][o(20)][k(64)] fp16; o-row = 128B line
__device__ uint4  g_h4[(size_t)EMAX * 8];      // h per edge, fp16 (64 halves = 8 uint4)
__device__ float  g_D[(size_t)NMAX * 20];      // b2 contribution per node
__device__ float  g_aggr[(size_t)NMAX * 20];   // scatter-add target
__device__ float  g_stats[160];                // [0..16): sum ea_i ; [16..152): upper-tri sum ea_i*ea_j
__device__ float  g_W1s[16 * 64];              // W1 with BN scale folded
__device__ float  g_shift[64];                 // BN shift
__device__ float  g_pool[GMAXC * 21];          // per-graph 20 sums + count

// ---------- k0: zero scratch ----------
__global__ void k0_zero(int N, int G) {
    int i = blockIdx.x * blockDim.x + threadIdx.x;
    int st = gridDim.x * blockDim.x;
    int na = N * 20;
    for (int t = i; t < na; t += st) g_aggr[t] = 0.f;
    for (int t = i; t < 160; t += st) g_stats[t] = 0.f;
    int np = G * 21;
    for (int t = i; t < np; t += st) g_pool[t] = 0.f;
}

// ---------- k1: edge_attr moments, register accumulation ----------
__global__ void __launch_bounds__(256, 1) k1_stats(const float* __restrict__ ea, int E) {
    float s[16];
    float p[136];
#pragma unroll
    for (int i = 0; i < 16; i++) s[i] = 0.f;
#pragma unroll
    for (int i = 0; i < 136; i++) p[i] = 0.f;

    int tid = blockIdx.x * blockDim.x + threadIdx.x;
    int stride = gridDim.x * blockDim.x;
    for (int e = tid; e < E; e += stride) {
        const float4* e4 = (const float4*)ea + (size_t)e * 4;
        float4 v0 = e4[0], v1 = e4[1], v2 = e4[2], v3 = e4[3];
        float ev[16] = {v0.x, v0.y, v0.z, v0.w, v1.x, v1.y, v1.z, v1.w,
                        v2.x, v2.y, v2.z, v2.w, v3.x, v3.y, v3.z, v3.w};
        int idx = 0;
#pragma unroll
        for (int i = 0; i < 16; i++) {
            s[i] += ev[i];
#pragma unroll
            for (int j = i; j < 16; j++) p[idx++] += ev[i] * ev[j];
        }
    }
    // warp reduce
#pragma unroll
    for (int i = 0; i < 16; i++) {
#pragma unroll
        for (int off = 16; off; off >>= 1) s[i] += __shfl_xor_sync(0xffffffffu, s[i], off);
    }
#pragma unroll
    for (int i = 0; i < 136; i++) {
#pragma unroll
        for (int off = 16; off; off >>= 1) p[i] += __shfl_xor_sync(0xffffffffu, p[i], off);
    }
    if ((threadIdx.x & 31) == 0) {
#pragma unroll
        for (int i = 0; i < 16; i++) atomicAdd(&g_stats[i], s[i]);
#pragma unroll
        for (int i = 0; i < 136; i++) atomicAdd(&g_stats[16 + i], p[i]);
    }
}

// ---------- k2: fold BN into W1s/shift ----------
__global__ void k2_prep(const float* __restrict__ W1, const float* __restrict__ gamma,
                        const float* __restrict__ beta, float Einv) {
    int k = threadIdx.x;
    if (k >= 64) return;
    float m[16], w[16];
#pragma unroll
    for (int i = 0; i < 16; i++) { m[i] = g_stats[i] * Einv; w[i] = W1[i * 64 + k]; }
    float mu = 0.f;
#pragma unroll
    for (int i = 0; i < 16; i++) mu += m[i] * w[i];
    float var = 0.f;
    int idx = 16;
    for (int i = 0; i < 16; i++)
        for (int j = i; j < 16; j++) {
            float c = g_stats[idx++] * Einv - m[i] * m[j];
            float ww = w[i] * w[j] * c;
            var += (i == j) ? ww : 2.f * ww;
        }
    float sc = gamma[k] * rsqrtf(var + BN_EPS);
    g_shift[k] = beta[k] - mu * sc;
#pragma unroll
    for (int i = 0; i < 16; i++) g_W1s[i * 64 + k] = w[i] * sc;
}

// ---------- k3: build P[n][o][k] fp16, f32x2 math ----------
// thread t: k = t&63, ob = t>>6; owns o in {ob, ob+4, ob+8, ob+12, ob+16}.
__global__ void __launch_bounds__(256) k3_P(const float* __restrict__ x,
                                            const float* __restrict__ W2, int N) {
    __shared__ u64 sx2[8 * 16];
    int t = threadIdx.x;
    int k = t & 63, ob = t >> 6;
    u64 wA[16], wB[16];
    float wC[16];
#pragma unroll
    for (int i = 0; i < 16; i++) {
        const float* wr = W2 + k * 320 + i * 20 + ob;
        wA[i] = pk2(wr[0], wr[4]);
        wB[i] = pk2(wr[8], wr[12]);
        wC[i] = wr[16];
    }
    __half* Ph = (__half*)g_P4;
    for (int n0 = blockIdx.x * 8; n0 < N; n0 += gridDim.x * 8) {
        int nn = min(8, N - n0);
        __syncthreads();
        for (int q = t; q < nn * 16; q += 256) {
            float v = x[(size_t)n0 * 16 + q];
            sx2[q] = pk2(v, v);
        }
        __syncthreads();
        for (int u = 0; u < nn; u++) {
            u64 aA = 0ull, aB = 0ull;
            float aC = 0.f;
#pragma unroll
            for (int i = 0; i < 16; i++) {
                u64 xv = sx2[u * 16 + i];
                fma2(aA, xv, wA[i]);
                fma2(aB, xv, wB[i]);
                aC += upk(xv).x * wC[i];
            }
            float2 fA = upk(aA), fB = upk(aB);
            size_t base = (size_t)(n0 + u) * 1280 + k;
            Ph[base + (size_t)ob * 64]        = __float2half(fA.x);
            Ph[base + (size_t)(ob + 4) * 64]  = __float2half(fA.y);
            Ph[base + (size_t)(ob + 8) * 64]  = __float2half(fB.x);
            Ph[base + (size_t)(ob + 12) * 64] = __float2half(fB.y);
            Ph[base + (size_t)(ob + 16) * 64] = __float2half(aC);
        }
    }
}

// ---------- k3b: D[n][o] = sum_i x[n,i] * b2[i*20+o] ----------
__global__ void k3b_D(const float* __restrict__ x, const float* __restrict__ b2, int N) {
    __shared__ float sb[320];
    for (int q = threadIdx.x; q < 320; q += blockDim.x) sb[q] = b2[q];
    __syncthreads();
    int id = blockIdx.x * blockDim.x + threadIdx.x;
    if (id >= N * 20) return;
    int n = id / 20, o = id % 20;
    const float* xr = x + (size_t)n * 16;
    float v = 0.f;
#pragma unroll
    for (int i = 0; i < 16; i++) v += xr[i] * sb[i * 20 + o];
    g_D[id] = v;
}

// ---------- k3c: h = relu(ea@W1s + shift) -> fp16; 2 edges per warp-iter, f32x2 ----------
__global__ void __launch_bounds__(256) k3c_h(const float* __restrict__ ea, int E) {
    int lane = threadIdx.x & 31;
    int k0 = lane * 2;
    u64 w0[16], w1[16];
#pragma unroll
    for (int i = 0; i < 16; i++) {
        float a = g_W1s[i * 64 + k0], b = g_W1s[i * 64 + k0 + 1];
        w0[i] = pk2(a, a);
        w1[i] = pk2(b, b);
    }
    float sh0 = g_shift[k0], sh1 = g_shift[k0 + 1];
    u64 sp0 = pk2(sh0, sh0), sp1 = pk2(sh1, sh1);

    int nw = gridDim.x * (blockDim.x >> 5);
    int wi = blockIdx.x * (blockDim.x >> 5) + (threadIdx.x >> 5);
    __half2* hp = (__half2*)g_h4;
    for (int e0 = wi * 2; e0 < E; e0 += nw * 2) {
        int e1 = (e0 + 1 < E) ? e0 + 1 : e0;
        const float4* a4 = (const float4*)ea + (size_t)e0 * 4;
        const float4* b4 = (const float4*)ea + (size_t)e1 * 4;
        float4 av[4] = {a4[0], a4[1], a4[2], a4[3]};
        float4 bv[4] = {b4[0], b4[1], b4[2], b4[3]};
        const float* af = (const float*)av;
        const float* bf = (const float*)bv;
        u64 acc0 = sp0, acc1 = sp1;
#pragma unroll
        for (int i = 0; i < 16; i++) {
            u64 xp = pk2(af[i], bf[i]);
            fma2(acc0, xp, w0[i]);
            fma2(acc1, xp, w1[i]);
        }
        float2 f0 = upk(acc0), f1 = upk(acc1);
        hp[(size_t)e0 * 32 + lane] = __floats2half2_rn(fmaxf(f0.x, 0.f), fmaxf(f1.x, 0.f));
        if (e0 + 1 < E)
            hp[(size_t)(e0 + 1) * 32 + lane] = __floats2half2_rn(fmaxf(f0.y, 0.f), fmaxf(f1.y, 0.f));
    }
}

// ---------- k4: per-edge msg + scatter-add (8 lanes/edge, chunked MLP) ----------
__global__ void __launch_bounds__(256) k4_edge(const int* __restrict__ ei, int E) {
    int tid = threadIdx.x;
    int r = tid & 7;
    int groups = gridDim.x * 32;
    for (int base = blockIdx.x * 32; base < E; base += groups) {
        int e = base + (tid >> 3);
        bool act = (e < E);
        int ec = act ? e : E - 1;
        int src = __ldg(ei + ec), dst = __ldg(ei + E + ec);
        // streamed h: evict-first so it doesn't displace L2-resident P
        uint4 hv = __ldcs(g_h4 + (size_t)ec * 8 + r);
        float hf[8];
        {
            __half2* hh = (__half2*)&hv;
#pragma unroll
            for (int i = 0; i < 4; i++) {
                float2 f = __half22float2(hh[i]);
                hf[2 * i] = f.x; hf[2 * i + 1] = f.y;
            }
        }
        const uint4* Pn = g_P4 + (size_t)src * 160;
        float msg0 = 0.f, msg1 = 0.f, msg2 = 0.f;
#pragma unroll
        for (int c = 0; c < 4; c++) {
            uint4 pv[5];
#pragma unroll
            for (int q = 0; q < 5; q++) pv[q] = Pn[(c * 5 + q) * 8 + r];
#pragma unroll
            for (int q = 0; q < 5; q++) {
                int o = c * 5 + q;
                __half2* pp = (__half2*)&pv[q];
                float s = 0.f;
#pragma unroll
                for (int i = 0; i < 4; i++) {
                    float2 f = __half22float2(pp[i]);
                    s += hf[2 * i] * f.x + hf[2 * i + 1] * f.y;
                }
                s += __shfl_xor_sync(0xffffffffu, s, 4);
                s += __shfl_xor_sync(0xffffffffu, s, 2);
                s += __shfl_xor_sync(0xffffffffu, s, 1);
                if ((o & 7) == r) {
                    if (o < 8) msg0 = s; else if (o < 16) msg1 = s; else msg2 = s;
                }
            }
        }
        if (act) {
            const float* Dn = g_D + (size_t)src * 20;
            float* An = g_aggr + (size_t)dst * 20;
            atomicAdd(An + r, msg0 + Dn[r]);
            atomicAdd(An + 8 + r, msg1 + Dn[8 + r]);
            if (r < 4) atomicAdd(An + 16 + r, msg2 + Dn[16 + r]);
        }
    }
}

// ---------- k5: out = x@root_w + aggr + bias; pool by sorted batch ----------
__global__ void k5_out(const float* __restrict__ x, const float* __restrict__ rw,
                       const float* __restrict__ bias, const int* __restrict__ batch, int N) {
    __shared__ float s_rw[320];
    __shared__ float s_b[20];
    int tid = threadIdx.x;
    for (int q = tid; q < 320; q += blockDim.x) s_rw[q] = rw[q];
    if (tid < 20) s_b[tid] = bias[tid];
    __syncthreads();
    int tau = blockIdx.x * blockDim.x + tid;
    int C = (N + 19) / 20;
    if (tau >= C * 20) return;
    int c = tau / 20, o = tau % 20;
    int curg = -1;
    float acc = 0.f, cnt = 0.f;
    for (int u = 0; u < 20; u++) {
        int n = c * 20 + u;
        if (n >= N) break;
        int g = batch[n];
        float v = s_b[o] + g_aggr[(size_t)n * 20 + o];
        const float4* xr4 = (const float4*)(x + (size_t)n * 16);
        float4 x0 = xr4[0], x1 = xr4[1], x2 = xr4[2], x3 = xr4[3];
        const float* xr = (const float*)&x0;  // contiguous locals
        float xv[16] = {x0.x, x0.y, x0.z, x0.w, x1.x, x1.y, x1.z, x1.w,
                        x2.x, x2.y, x2.z, x2.w, x3.x, x3.y, x3.z, x3.w};
        (void)xr;
#pragma unroll
        for (int i = 0; i < 16; i++) v += xv[i] * s_rw[i * 20 + o];
        if (g != curg) {
            if (curg >= 0) {
                atomicAdd(&g_pool[curg * 21 + o], acc);
                if (o == 0) atomicAdd(&g_pool[curg * 21 + 20], cnt);
            }
            curg = g; acc = 0.f; cnt = 0.f;
        }
        acc += v; cnt += 1.f;
    }
    if (curg >= 0) {
        atomicAdd(&g_pool[curg * 21 + o], acc);
        if (o == 0) atomicAdd(&g_pool[curg * 21 + 20], cnt);
    }
}

// ---------- k6: critic head, one block per graph ----------
__global__ void __launch_bounds__(256) k6_critic(const float* __restrict__ a,
                                                 const float* __restrict__ Wc1,
                                                 const float* __restrict__ bc1,
                                                 const float* __restrict__ Wc2,
                                                 const float* __restrict__ bc2,
                                                 float* __restrict__ out) {
    int g = blockIdx.x;
    int tid = threadIdx.x;
    __shared__ float sz[28];
    __shared__ float sp[8];
    if (tid < 28) {
        if (tid < 20) {
            float cnt = g_pool[g * 21 + 20];
            float inv = 1.f / fmaxf(cnt, 1.f);
            sz[tid] = g_pool[g * 21 + tid] * inv;
        } else {
            sz[tid] = a[g * 8 + tid - 20];
        }
    }
    __syncthreads();
    float v = bc1[tid];
#pragma unroll
    for (int i = 0; i < 28; i++) v += sz[i] * Wc1[i * 256 + tid];
    v = fmaxf(v, 0.f);
    float p = v * Wc2[tid];
#pragma unroll
    for (int off = 16; off; off >>= 1) p += __shfl_xor_sync(0xffffffffu, p, off);
    if ((tid & 31) == 0) sp[tid >> 5] = p;
    __syncthreads();
    if (tid == 0) {
        float t = 0.f;
        for (int w = 0; w < 8; w++) t += sp[w];
        out[g] = t + bc2[0];
    }
}

// ---------- launch ----------
extern "C" void kernel_launch(void* const* d_in, const int* in_sizes, int n_in,
                              void* d_out, int out_size) {
    int N = in_sizes[0] / 16;
    int E = in_sizes[1] / 16;
    int G = out_size;

    const float *x = (const float*)d_in[0];
    const float *ea = (const float*)d_in[1];
    const float *a = (const float*)d_in[2];
    const float *W1, *gamma, *beta, *W2, *b2, *rw, *bias, *Wc1, *bc1, *Wc2, *bc2;
    const int *ei, *batch;

    bool dict_order = (n_in > 4 && in_sizes[3] == 2 * E);
    if (dict_order) {
        ei    = (const int*)d_in[3];
        batch = (const int*)d_in[4];
        W1    = (const float*)d_in[5];
        gamma = (const float*)d_in[7];
        beta  = (const float*)d_in[8];
        W2    = (const float*)d_in[9];
        b2    = (const float*)d_in[10];
        rw    = (const float*)d_in[11];
        bias  = (const float*)d_in[12];
        Wc1   = (const float*)d_in[13];
        bc1   = (const float*)d_in[14];
        Wc2   = (const float*)d_in[15];
        bc2   = (const float*)d_in[16];
    } else {
        W1    = (const float*)d_in[3];
        gamma = (const float*)d_in[5];
        beta  = (const float*)d_in[6];
        W2    = (const float*)d_in[7];
        b2    = (const float*)d_in[8];
        rw    = (const float*)d_in[9];
        bias  = (const float*)d_in[10];
        Wc1   = (const float*)d_in[11];
        bc1   = (const float*)d_in[12];
        Wc2   = (const float*)d_in[13];
        bc2   = (const float*)d_in[14];
        ei    = (const int*)d_in[15];
        batch = (const int*)d_in[16];
    }

    float* out = (float*)d_out;

    k0_zero<<<296, 256>>>(N, G);
    k1_stats<<<148, 256>>>(ea, E);
    k2_prep<<<1, 64>>>(W1, gamma, beta, 1.0f / (float)E);
    k3_P<<<592, 256>>>(x, W2, N);
    k3b_D<<<(N * 20 + 255) / 256, 256>>>(x, b2, N);
    k3c_h<<<1184, 256>>>(ea, E);
    k4_edge<<<1184, 256>>>(ei, E);
    {
        int C = (N + 19) / 20;
        k5_out<<<(C * 20 + 255) / 256, 256>>>(x, rw, bias, batch, N);
    }
    k6_critic<<<G, 256>>>(a, Wc1, bc1, Wc2, bc2, out);
}

// round 4
// speedup vs baseline: 1.0695x; 1.0695x over previous
#include <cuda_runtime.h>
#include <cuda_fp16.h>

#define NMAX 50000
#define EMAX 800000
#define GMAXC 64
#define BN_EPS 1e-5f

// ---------- static device scratch (no allocation allowed) ----------
__device__ uint4  g_P4[(size_t)NMAX * 160];    // P: [n][o(20)][k(64)] fp16; o-row = 128B line
__device__ uint4  g_h4[(size_t)EMAX * 8];      // h per edge, fp16 (64 halves = 8 uint4)
__device__ float  g_D[(size_t)NMAX * 20];      // b2 contribution per node
__device__ float  g_aggr[(size_t)NMAX * 20];   // scatter-add target
__device__ float  g_stats[160];                // [0..16): sum ea_i ; [16..152): upper-tri products
__device__ float  g_W1s[16 * 64];              // W1 with BN scale folded
__device__ float  g_shift[64];                 // BN shift
__device__ float  g_pool[GMAXC * 21];          // per-graph 20 sums + count
// counting-sort scratch
__device__ int    g_cnt[NMAX + 1];
__device__ int    g_start[NMAX + 1];
__device__ int    g_cursor[NMAX];
__device__ int    g_eperm[EMAX];
__device__ int    g_edst[EMAX];

// ---------- k0: zero scratch ----------
__global__ void k0_zero(int N, int G) {
    int i = blockIdx.x * blockDim.x + threadIdx.x;
    int st = gridDim.x * blockDim.x;
    int na = N * 20;
    for (int t = i; t < na; t += st) g_aggr[t] = 0.f;
    for (int t = i; t < 160; t += st) g_stats[t] = 0.f;
    int np = G * 21;
    for (int t = i; t < np; t += st) g_pool[t] = 0.f;
    for (int t = i; t <= N; t += st) g_cnt[t] = 0;
}

// ---------- k1: edge_attr first/second moments (smem-tiled) ----------
__global__ void __launch_bounds__(256) k1_stats(const float* __restrict__ ea, int E) {
    __shared__ float sEA[128 * 17];
    int tid = threadIdx.x;
    int ji = 0, jj = 0;
    bool is_mean = false, is_pair = false;
    if (tid < 16) { ji = tid; is_mean = true; }
    else if (tid < 152) {
        int p = tid - 16, i = 0, c = 16;
        while (p >= c) { p -= c; i++; c--; }
        ji = i; jj = i + p; is_pair = true;
    }
    float acc = 0.f;
    int ntiles = (E + 127) >> 7;
    for (int t = blockIdx.x; t < ntiles; t += gridDim.x) {
        int base = t << 7;
        __syncthreads();
        for (int q = tid; q < 2048; q += blockDim.x) {
            int el = q >> 4, i = q & 15;
            int e = base + el;
            sEA[el * 17 + i] = (e < E) ? ea[(size_t)e * 16 + i] : 0.f;
        }
        __syncthreads();
        if (is_mean) {
            for (int e2 = 0; e2 < 128; e2++) acc += sEA[e2 * 17 + ji];
        } else if (is_pair) {
            for (int e2 = 0; e2 < 128; e2++) acc += sEA[e2 * 17 + ji] * sEA[e2 * 17 + jj];
        }
    }
    if (tid < 152) atomicAdd(&g_stats[tid], acc);
}

// ---------- k2: fold BN into W1s/shift ----------
__global__ void k2_prep(const float* __restrict__ W1, const float* __restrict__ gamma,
                        const float* __restrict__ beta, float Einv) {
    int k = threadIdx.x;
    if (k >= 64) return;
    float m[16], w[16];
#pragma unroll
    for (int i = 0; i < 16; i++) { m[i] = g_stats[i] * Einv; w[i] = W1[i * 64 + k]; }
    float mu = 0.f;
#pragma unroll
    for (int i = 0; i < 16; i++) mu += m[i] * w[i];
    float var = 0.f;
    int idx = 16;
    for (int i = 0; i < 16; i++)
        for (int j = i; j < 16; j++) {
            float c = g_stats[idx++] * Einv - m[i] * m[j];
            float ww = w[i] * w[j] * c;
            var += (i == j) ? ww : 2.f * ww;
        }
    float sc = gamma[k] * rsqrtf(var + BN_EPS);
    g_shift[k] = beta[k] - mu * sc;
#pragma unroll
    for (int i = 0; i < 16; i++) g_W1s[i * 64 + k] = w[i] * sc;
}

// ---------- sort: histogram by src ----------
__global__ void ks_hist(const int* __restrict__ ei, int E) {
    int i = blockIdx.x * blockDim.x + threadIdx.x;
    if (i < E) atomicAdd(&g_cnt[ei[i]], 1);
}

// ---------- sort: exclusive scan over g_cnt (single block, chunked) ----------
__global__ void __launch_bounds__(1024) ks_scan(int N) {
    __shared__ int sbuf[2048];
    __shared__ int s_carry;
    int tid = threadIdx.x;
    if (tid == 0) s_carry = 0;
    __syncthreads();
    for (int base = 0; base < N; base += 1024) {
        int idx = base + tid;
        int v = (idx < N) ? g_cnt[idx] : 0;
        sbuf[tid] = v;
        __syncthreads();
        int a = 0, b = 1024;
        for (int off = 1; off < 1024; off <<= 1) {
            int nv = sbuf[a + tid];
            if (tid >= off) nv += sbuf[a + tid - off];
            sbuf[b + tid] = nv;
            __syncthreads();
            int t2 = a; a = b; b = t2;
        }
        int incl = sbuf[a + tid];
        int c = s_carry;
        if (idx < N) {
            int excl = incl - v + c;
            g_start[idx] = excl;
            g_cursor[idx] = excl;
        }
        __syncthreads();
        if (tid == 1023) s_carry = c + incl;
        __syncthreads();
    }
    if (tid == 0) g_start[N] = s_carry;
}

// ---------- sort: scatter edge ids + dst into grouped order ----------
__global__ void ks_scatter(const int* __restrict__ ei, int E) {
    int i = blockIdx.x * blockDim.x + threadIdx.x;
    if (i >= E) return;
    int s = ei[i];
    int pos = atomicAdd(&g_cursor[s], 1);
    g_eperm[pos] = i;
    g_edst[pos] = ei[E + i];
}

// ---------- k3: build P[n][o][k] fp16 ----------
__global__ void __launch_bounds__(256) k3_P(const float* __restrict__ x,
                                            const float* __restrict__ W2, int N) {
    __shared__ float sx[8 * 16];
    int t = threadIdx.x;
    int k = t & 63, ob = t >> 6;
    float w[5][16];
#pragma unroll
    for (int j = 0; j < 5; j++) {
        int o = ob + 4 * j;
#pragma unroll
        for (int i = 0; i < 16; i++) w[j][i] = W2[k * 320 + i * 20 + o];
    }
    __half* Ph = (__half*)g_P4;
    for (int n0 = blockIdx.x * 8; n0 < N; n0 += gridDim.x * 8) {
        int nn = min(8, N - n0);
        __syncthreads();
        for (int q = t; q < nn * 16; q += 256) sx[q] = x[(size_t)n0 * 16 + q];
        __syncthreads();
        for (int u = 0; u < nn; u++) {
            int n = n0 + u;
            float acc[5] = {0.f, 0.f, 0.f, 0.f, 0.f};
#pragma unroll
            for (int i = 0; i < 16; i++) {
                float xv = sx[u * 16 + i];
#pragma unroll
                for (int j = 0; j < 5; j++) acc[j] += xv * w[j][i];
            }
#pragma unroll
            for (int j = 0; j < 5; j++) {
                int o = ob + 4 * j;
                Ph[(size_t)n * 1280 + o * 64 + k] = __float2half(acc[j]);
            }
        }
    }
}

// ---------- k3b: D[n][o] = sum_i x[n,i] * b2[i*20+o] ----------
__global__ void k3b_D(const float* __restrict__ x, const float* __restrict__ b2, int N) {
    __shared__ float sb[320];
    for (int q = threadIdx.x; q < 320; q += blockDim.x) sb[q] = b2[q];
    __syncthreads();
    int id = blockIdx.x * blockDim.x + threadIdx.x;
    if (id >= N * 20) return;
    int n = id / 20, o = id % 20;
    const float* xr = x + (size_t)n * 16;
    float v = 0.f;
#pragma unroll
    for (int i = 0; i < 16; i++) v += xr[i] * sb[i * 20 + o];
    g_D[id] = v;
}

// ---------- k3c: h[e][k] = relu(ea[e]@W1s + shift) -> fp16 (warp/edge) ----------
__global__ void __launch_bounds__(256) k3c_h(const float* __restrict__ ea, int E) {
    int lane = threadIdx.x & 31;
    int k0 = lane * 2;
    float w0[16], w1[16];
#pragma unroll
    for (int i = 0; i < 16; i++) { w0[i] = g_W1s[i * 64 + k0]; w1[i] = g_W1s[i * 64 + k0 + 1]; }
    float sh0 = g_shift[k0], sh1 = g_shift[k0 + 1];
    int nw = gridDim.x * (blockDim.x >> 5);
    int wi = blockIdx.x * (blockDim.x >> 5) + (threadIdx.x >> 5);
    __half2* hp = (__half2*)g_h4;
    for (int e = wi; e < E; e += nw) {
        const float4* e4 = (const float4*)ea + (size_t)e * 4;
        float4 v0 = e4[0], v1 = e4[1], v2 = e4[2], v3 = e4[3];
        float ev[16] = {v0.x, v0.y, v0.z, v0.w, v1.x, v1.y, v1.z, v1.w,
                        v2.x, v2.y, v2.z, v2.w, v3.x, v3.y, v3.z, v3.w};
        float h0 = sh0, h1 = sh1;
#pragma unroll
        for (int i = 0; i < 16; i++) { h0 += ev[i] * w0[i]; h1 += ev[i] * w1[i]; }
        hp[(size_t)e * 32 + lane] = __floats2half2_rn(fmaxf(h0, 0.f), fmaxf(h1, 0.f));
    }
}

// ---------- k4: warp-per-node grouped msg + scatter-add ----------
// lane l: m = l>>3 selects o-quad base, r = l&7 selects k-chunk (8 halves).
// P uint4 index j = l + 32t covers o = m + 4t, k-chunk r. After 8-lane xor-reduce,
// lane with r=t (<5) owns msg[m+4t] and issues the atomic.
__global__ void __launch_bounds__(256) k4_nodes(int N) {
    int wg = (blockIdx.x * blockDim.x + threadIdx.x) >> 5;
    int lane = threadIdx.x & 31;
    if (wg >= N) return;
    int n = wg;
    int s = g_start[n], epos_end = g_start[n + 1];
    if (s == epos_end) return;
    int m = lane >> 3, r = lane & 7;

    const uint4* Pn = g_P4 + (size_t)n * 160;
    float pf[5][8];
#pragma unroll
    for (int t = 0; t < 5; t++) {
        uint4 pv = Pn[lane + 32 * t];
        __half2* pp = (__half2*)&pv;
#pragma unroll
        for (int i = 0; i < 4; i++) {
            float2 f = __half22float2(pp[i]);
            pf[t][2 * i] = f.x; pf[t][2 * i + 1] = f.y;
        }
    }
    float dval = (r < 5) ? g_D[(size_t)n * 20 + m + 4 * r] : 0.f;

    int pos = s;
    int d0 = g_edst[pos];
    uint4 h0v = __ldcs(g_h4 + (size_t)g_eperm[pos] * 8 + r);
    while (pos < epos_end) {
        int nxt = pos + 1;
        int d1 = 0;
        uint4 h1v = h0v;
        if (nxt < epos_end) {
            d1 = g_edst[nxt];
            h1v = __ldcs(g_h4 + (size_t)g_eperm[nxt] * 8 + r);
        }
        float hf[8];
        {
            __half2* hh = (__half2*)&h0v;
#pragma unroll
            for (int i = 0; i < 4; i++) {
                float2 f = __half22float2(hh[i]);
                hf[2 * i] = f.x; hf[2 * i + 1] = f.y;
            }
        }
        float s0, s1, s2, s3, s4;
        {
            float a0 = 0.f, a1 = 0.f, a2 = 0.f, a3 = 0.f, a4 = 0.f;
#pragma unroll
            for (int i = 0; i < 8; i++) {
                float hv = hf[i];
                a0 += hv * pf[0][i];
                a1 += hv * pf[1][i];
                a2 += hv * pf[2][i];
                a3 += hv * pf[3][i];
                a4 += hv * pf[4][i];
            }
#pragma unroll
            for (int off = 1; off <= 4; off <<= 1) {
                a0 += __shfl_xor_sync(0xffffffffu, a0, off);
                a1 += __shfl_xor_sync(0xffffffffu, a1, off);
                a2 += __shfl_xor_sync(0xffffffffu, a2, off);
                a3 += __shfl_xor_sync(0xffffffffu, a3, off);
                a4 += __shfl_xor_sync(0xffffffffu, a4, off);
            }
            s0 = a0; s1 = a1; s2 = a2; s3 = a3; s4 = a4;
        }
        if (r < 5) {
            float v = s0;
            if (r == 1) v = s1;
            else if (r == 2) v = s2;
            else if (r == 3) v = s3;
            else if (r == 4) v = s4;
            atomicAdd(&g_aggr[(size_t)d0 * 20 + m + 4 * r], v + dval);
        }
        pos = nxt; h0v = h1v; d0 = d1;
    }
}

// ---------- k5: out = x@root_w + aggr + bias; pool by sorted batch ----------
__global__ void k5_out(const float* __restrict__ x, const float* __restrict__ rw,
                       const float* __restrict__ bias, const int* __restrict__ batch, int N) {
    __shared__ float s_rw[320];
    __shared__ float s_b[20];
    int tid = threadIdx.x;
    for (int q = tid; q < 320; q += blockDim.x) s_rw[q] = rw[q];
    if (tid < 20) s_b[tid] = bias[tid];
    __syncthreads();
    int tau = blockIdx.x * blockDim.x + tid;
    int C = (N + 19) / 20;
    if (tau >= C * 20) return;
    int c = tau / 20, o = tau % 20;
    int curg = -1;
    float acc = 0.f, cnt = 0.f;
    for (int u = 0; u < 20; u++) {
        int n = c * 20 + u;
        if (n >= N) break;
        int g = batch[n];
        float v = s_b[o] + g_aggr[(size_t)n * 20 + o];
        const float* xr = x + (size_t)n * 16;
#pragma unroll
        for (int i = 0; i < 16; i++) v += xr[i] * s_rw[i * 20 + o];
        if (g != curg) {
            if (curg >= 0) {
                atomicAdd(&g_pool[curg * 21 + o], acc);
                if (o == 0) atomicAdd(&g_pool[curg * 21 + 20], cnt);
            }
            curg = g; acc = 0.f; cnt = 0.f;
        }
        acc += v; cnt += 1.f;
    }
    if (curg >= 0) {
        atomicAdd(&g_pool[curg * 21 + o], acc);
        if (o == 0) atomicAdd(&g_pool[curg * 21 + 20], cnt);
    }
}

// ---------- k6: critic head, one block per graph ----------
__global__ void __launch_bounds__(256) k6_critic(const float* __restrict__ a,
                                                 const float* __restrict__ Wc1,
                                                 const float* __restrict__ bc1,
                                                 const float* __restrict__ Wc2,
                                                 const float* __restrict__ bc2,
                                                 float* __restrict__ out) {
    int g = blockIdx.x;
    int tid = threadIdx.x;
    __shared__ float sz[28];
    __shared__ float sp[8];
    if (tid < 28) {
        if (tid < 20) {
            float cnt = g_pool[g * 21 + 20];
            float inv = 1.f / fmaxf(cnt, 1.f);
            sz[tid] = g_pool[g * 21 + tid] * inv;
        } else {
            sz[tid] = a[g * 8 + tid - 20];
        }
    }
    __syncthreads();
    float v = bc1[tid];
#pragma unroll
    for (int i = 0; i < 28; i++) v += sz[i] * Wc1[i * 256 + tid];
    v = fmaxf(v, 0.f);
    float p = v * Wc2[tid];
#pragma unroll
    for (int off = 16; off; off >>= 1) p += __shfl_xor_sync(0xffffffffu, p, off);
    if ((tid & 31) == 0) sp[tid >> 5] = p;
    __syncthreads();
    if (tid == 0) {
        float t = 0.f;
        for (int w = 0; w < 8; w++) t += sp[w];
        out[g] = t + bc2[0];
    }
}

// ---------- launch ----------
extern "C" void kernel_launch(void* const* d_in, const int* in_sizes, int n_in,
                              void* d_out, int out_size) {
    int N = in_sizes[0] / 16;
    int E = in_sizes[1] / 16;
    int G = out_size;

    const float *x = (const float*)d_in[0];
    const float *ea = (const float*)d_in[1];
    const float *a = (const float*)d_in[2];
    const float *W1, *gamma, *beta, *W2, *b2, *rw, *bias, *Wc1, *bc1, *Wc2, *bc2;
    const int *ei, *batch;

    bool dict_order = (n_in > 4 && in_sizes[3] == 2 * E);
    if (dict_order) {
        ei    = (const int*)d_in[3];
        batch = (const int*)d_in[4];
        W1    = (const float*)d_in[5];
        gamma = (const float*)d_in[7];
        beta  = (const float*)d_in[8];
        W2    = (const float*)d_in[9];
        b2    = (const float*)d_in[10];
        rw    = (const float*)d_in[11];
        bias  = (const float*)d_in[12];
        Wc1   = (const float*)d_in[13];
        bc1   = (const float*)d_in[14];
        Wc2   = (const float*)d_in[15];
        bc2   = (const float*)d_in[16];
    } else {
        W1    = (const float*)d_in[3];
        gamma = (const float*)d_in[5];
        beta  = (const float*)d_in[6];
        W2    = (const float*)d_in[7];
        b2    = (const float*)d_in[8];
        rw    = (const float*)d_in[9];
        bias  = (const float*)d_in[10];
        Wc1   = (const float*)d_in[11];
        bc1   = (const float*)d_in[12];
        Wc2   = (const float*)d_in[13];
        bc2   = (const float*)d_in[14];
        ei    = (const int*)d_in[15];
        batch = (const int*)d_in[16];
    }

    float* out = (float*)d_out;

    k0_zero<<<1024, 256>>>(N, G);
    {
        int ntiles = (E + 127) >> 7;
        int grid = ntiles < 1184 ? ntiles : 1184;
        k1_stats<<<grid, 256>>>(ea, E);
    }
    k2_prep<<<1, 64>>>(W1, gamma, beta, 1.0f / (float)E);
    ks_hist<<<(E + 255) / 256, 256>>>(ei, E);
    ks_scan<<<1, 1024>>>(N);
    ks_scatter<<<(E + 255) / 256, 256>>>(ei, E);
    k3_P<<<592, 256>>>(x, W2, N);
    k3b_D<<<(N * 20 + 255) / 256, 256>>>(x, b2, N);
    k3c_h<<<1184, 256>>>(ea, E);
    k4_nodes<<<(N + 7) / 8, 256>>>(N);
    {
        int C = (N + 19) / 20;
        k5_out<<<(C * 20 + 255) / 256, 256>>>(x, rw, bias, batch, N);
    }
    k6_critic<<<G, 256>>>(a, Wc1, bc1, Wc2, bc2, out);
}

// round 5
// speedup vs baseline: 1.1138x; 1.0415x over previous
#include <cuda_runtime.h>
#include <cuda_fp16.h>

#define NMAX 50000
#define EMAX 800000
#define GMAXC 64
#define BN_EPS 1e-5f

// ---------- static device scratch (no allocation allowed) ----------
__device__ uint4  g_P4[(size_t)NMAX * 160];    // P: [n][o(20)][k(64)] fp16; o-row = 128B line
__device__ uint4  g_h4[(size_t)EMAX * 8];      // h in SORTED position order, fp16
__device__ float  g_D[(size_t)NMAX * 20];      // b2 contribution per node
__device__ float  g_aggr[(size_t)NMAX * 20];   // scatter-add target
__device__ float  g_stats[160];                // [0..16): sum ea_i ; [16..152): upper-tri products
__device__ float  g_W1s[16 * 64];              // W1 with BN scale folded
__device__ float  g_shift[64];                 // BN shift
__device__ float  g_pool[GMAXC * 21];          // per-graph 20 sums + count
// counting-sort scratch
__device__ int    g_cnt[NMAX + 1];
__device__ int    g_start[NMAX + 1];
__device__ int    g_cursor[NMAX];
__device__ int    g_eperm[EMAX];
__device__ int    g_edst[EMAX];

// ---------- k0: zero scratch ----------
__global__ void k0_zero(int N, int G) {
    int i = blockIdx.x * blockDim.x + threadIdx.x;
    int st = gridDim.x * blockDim.x;
    int na = N * 20;
    for (int t = i; t < na; t += st) g_aggr[t] = 0.f;
    for (int t = i; t < 160; t += st) g_stats[t] = 0.f;
    int np = G * 21;
    for (int t = i; t < np; t += st) g_pool[t] = 0.f;
    for (int t = i; t <= N; t += st) g_cnt[t] = 0;
}

// ---------- k1: edge_attr moments, register outer-product + block reduce ----------
__global__ void __launch_bounds__(256) k1_stats(const float* __restrict__ ea, int E) {
    __shared__ float sred[8 * 152];
    float s[16];
    float p[136];
#pragma unroll
    for (int i = 0; i < 16; i++) s[i] = 0.f;
#pragma unroll
    for (int i = 0; i < 136; i++) p[i] = 0.f;

    int tid = blockIdx.x * blockDim.x + threadIdx.x;
    int stride = gridDim.x * blockDim.x;
    for (int e = tid; e < E; e += stride) {
        const float4* e4 = (const float4*)ea + (size_t)e * 4;
        float4 v0 = e4[0], v1 = e4[1], v2 = e4[2], v3 = e4[3];
        float ev[16] = {v0.x, v0.y, v0.z, v0.w, v1.x, v1.y, v1.z, v1.w,
                        v2.x, v2.y, v2.z, v2.w, v3.x, v3.y, v3.z, v3.w};
        int idx = 0;
#pragma unroll
        for (int i = 0; i < 16; i++) {
            s[i] += ev[i];
#pragma unroll
            for (int j = i; j < 16; j++) p[idx++] += ev[i] * ev[j];
        }
    }
    // warp reduce all accumulators
#pragma unroll
    for (int i = 0; i < 16; i++) {
#pragma unroll
        for (int off = 16; off; off >>= 1) s[i] += __shfl_xor_sync(0xffffffffu, s[i], off);
    }
#pragma unroll
    for (int i = 0; i < 136; i++) {
#pragma unroll
        for (int off = 16; off; off >>= 1) p[i] += __shfl_xor_sync(0xffffffffu, p[i], off);
    }
    int wid = threadIdx.x >> 5, lane = threadIdx.x & 31;
    if (lane == 0) {
#pragma unroll
        for (int i = 0; i < 16; i++) sred[wid * 152 + i] = s[i];
#pragma unroll
        for (int i = 0; i < 136; i++) sred[wid * 152 + 16 + i] = p[i];
    }
    __syncthreads();
    if (threadIdx.x < 152) {
        float v = 0.f;
#pragma unroll
        for (int w = 0; w < 8; w++) v += sred[w * 152 + threadIdx.x];
        atomicAdd(&g_stats[threadIdx.x], v);
    }
}

// ---------- k2: fold BN into W1s/shift ----------
__global__ void k2_prep(const float* __restrict__ W1, const float* __restrict__ gamma,
                        const float* __restrict__ beta, float Einv) {
    int k = threadIdx.x;
    if (k >= 64) return;
    float m[16], w[16];
#pragma unroll
    for (int i = 0; i < 16; i++) { m[i] = g_stats[i] * Einv; w[i] = W1[i * 64 + k]; }
    float mu = 0.f;
#pragma unroll
    for (int i = 0; i < 16; i++) mu += m[i] * w[i];
    float var = 0.f;
    int idx = 16;
    for (int i = 0; i < 16; i++)
        for (int j = i; j < 16; j++) {
            float c = g_stats[idx++] * Einv - m[i] * m[j];
            float ww = w[i] * w[j] * c;
            var += (i == j) ? ww : 2.f * ww;
        }
    float sc = gamma[k] * rsqrtf(var + BN_EPS);
    g_shift[k] = beta[k] - mu * sc;
#pragma unroll
    for (int i = 0; i < 16; i++) g_W1s[i * 64 + k] = w[i] * sc;
}

// ---------- sort: histogram by src ----------
__global__ void ks_hist(const int* __restrict__ ei, int E) {
    int i = blockIdx.x * blockDim.x + threadIdx.x;
    if (i < E) atomicAdd(&g_cnt[ei[i]], 1);
}

// ---------- sort: exclusive scan over g_cnt (single block, chunked) ----------
__global__ void __launch_bounds__(1024) ks_scan(int N) {
    __shared__ int sbuf[2048];
    __shared__ int s_carry;
    int tid = threadIdx.x;
    if (tid == 0) s_carry = 0;
    __syncthreads();
    for (int base = 0; base < N; base += 1024) {
        int idx = base + tid;
        int v = (idx < N) ? g_cnt[idx] : 0;
        sbuf[tid] = v;
        __syncthreads();
        int a = 0, b = 1024;
        for (int off = 1; off < 1024; off <<= 1) {
            int nv = sbuf[a + tid];
            if (tid >= off) nv += sbuf[a + tid - off];
            sbuf[b + tid] = nv;
            __syncthreads();
            int t2 = a; a = b; b = t2;
        }
        int incl = sbuf[a + tid];
        int c = s_carry;
        if (idx < N) {
            int excl = incl - v + c;
            g_start[idx] = excl;
            g_cursor[idx] = excl;
        }
        __syncthreads();
        if (tid == 1023) s_carry = c + incl;
        __syncthreads();
    }
    if (tid == 0) g_start[N] = s_carry;
}

// ---------- sort: scatter edge ids + dst into grouped order ----------
__global__ void ks_scatter(const int* __restrict__ ei, int E) {
    int i = blockIdx.x * blockDim.x + threadIdx.x;
    if (i >= E) return;
    int s = ei[i];
    int pos = atomicAdd(&g_cursor[s], 1);
    g_eperm[pos] = i;
    g_edst[pos] = ei[E + i];
}

// ---------- k3: build P[n][o][k] fp16 ----------
__global__ void __launch_bounds__(256) k3_P(const float* __restrict__ x,
                                            const float* __restrict__ W2, int N) {
    __shared__ float sx[8 * 16];
    int t = threadIdx.x;
    int k = t & 63, ob = t >> 6;
    float w[5][16];
#pragma unroll
    for (int j = 0; j < 5; j++) {
        int o = ob + 4 * j;
#pragma unroll
        for (int i = 0; i < 16; i++) w[j][i] = W2[k * 320 + i * 20 + o];
    }
    __half* Ph = (__half*)g_P4;
    for (int n0 = blockIdx.x * 8; n0 < N; n0 += gridDim.x * 8) {
        int nn = min(8, N - n0);
        __syncthreads();
        for (int q = t; q < nn * 16; q += 256) sx[q] = x[(size_t)n0 * 16 + q];
        __syncthreads();
        for (int u = 0; u < nn; u++) {
            int n = n0 + u;
            float acc[5] = {0.f, 0.f, 0.f, 0.f, 0.f};
#pragma unroll
            for (int i = 0; i < 16; i++) {
                float xv = sx[u * 16 + i];
#pragma unroll
                for (int j = 0; j < 5; j++) acc[j] += xv * w[j][i];
            }
#pragma unroll
            for (int j = 0; j < 5; j++) {
                int o = ob + 4 * j;
                Ph[(size_t)n * 1280 + o * 64 + k] = __float2half(acc[j]);
            }
        }
    }
}

// ---------- k3b: D[n][o] = sum_i x[n,i] * b2[i*20+o] ----------
__global__ void k3b_D(const float* __restrict__ x, const float* __restrict__ b2, int N) {
    __shared__ float sb[320];
    for (int q = threadIdx.x; q < 320; q += blockDim.x) sb[q] = b2[q];
    __syncthreads();
    int id = blockIdx.x * blockDim.x + threadIdx.x;
    if (id >= N * 20) return;
    int n = id / 20, o = id % 20;
    const float* xr = x + (size_t)n * 16;
    float v = 0.f;
#pragma unroll
    for (int i = 0; i < 16; i++) v += xr[i] * sb[i * 20 + o];
    g_D[id] = v;
}

// ---------- k3c: h in SORTED order: h[pos] = relu(ea[eperm[pos]]@W1s + shift) ----------
__global__ void __launch_bounds__(256) k3c_h(const float* __restrict__ ea, int E) {
    int lane = threadIdx.x & 31;
    int k0 = lane * 2;
    float w0[16], w1[16];
#pragma unroll
    for (int i = 0; i < 16; i++) { w0[i] = g_W1s[i * 64 + k0]; w1[i] = g_W1s[i * 64 + k0 + 1]; }
    float sh0 = g_shift[k0], sh1 = g_shift[k0 + 1];
    int nw = gridDim.x * (blockDim.x >> 5);
    int wi = blockIdx.x * (blockDim.x >> 5) + (threadIdx.x >> 5);
    __half2* hp = (__half2*)g_h4;
    for (int pos = wi; pos < E; pos += nw) {
        int e = g_eperm[pos];
        const float4* e4 = (const float4*)ea + (size_t)e * 4;
        float4 v0 = e4[0], v1 = e4[1], v2 = e4[2], v3 = e4[3];
        float ev[16] = {v0.x, v0.y, v0.z, v0.w, v1.x, v1.y, v1.z, v1.w,
                        v2.x, v2.y, v2.z, v2.w, v3.x, v3.y, v3.z, v3.w};
        float h0 = sh0, h1 = sh1;
#pragma unroll
        for (int i = 0; i < 16; i++) { h0 += ev[i] * w0[i]; h1 += ev[i] * w1[i]; }
        hp[(size_t)pos * 32 + lane] = __floats2half2_rn(fmaxf(h0, 0.f), fmaxf(h1, 0.f));
    }
}

// ---------- k4: warp-per-node grouped msg + scatter-add (h streamed sequentially) ----------
__global__ void __launch_bounds__(256) k4_nodes(int N) {
    int wg = (blockIdx.x * blockDim.x + threadIdx.x) >> 5;
    int lane = threadIdx.x & 31;
    if (wg >= N) return;
    int n = wg;
    int s = g_start[n], epos_end = g_start[n + 1];
    if (s == epos_end) return;
    int m = lane >> 3, r = lane & 7;

    const uint4* Pn = g_P4 + (size_t)n * 160;
    float pf[5][8];
#pragma unroll
    for (int t = 0; t < 5; t++) {
        uint4 pv = Pn[lane + 32 * t];
        __half2* pp = (__half2*)&pv;
#pragma unroll
        for (int i = 0; i < 4; i++) {
            float2 f = __half22float2(pp[i]);
            pf[t][2 * i] = f.x; pf[t][2 * i + 1] = f.y;
        }
    }
    float dval = (r < 5) ? g_D[(size_t)n * 20 + m + 4 * r] : 0.f;

    int pos = s;
    int d0 = g_edst[pos];
    uint4 h0v = __ldcs(g_h4 + (size_t)pos * 8 + r);
    while (pos < epos_end) {
        int nxt = pos + 1;
        int d1 = 0;
        uint4 h1v = h0v;
        if (nxt < epos_end) {
            d1 = g_edst[nxt];
            h1v = __ldcs(g_h4 + (size_t)nxt * 8 + r);
        }
        float hf[8];
        {
            __half2* hh = (__half2*)&h0v;
#pragma unroll
            for (int i = 0; i < 4; i++) {
                float2 f = __half22float2(hh[i]);
                hf[2 * i] = f.x; hf[2 * i + 1] = f.y;
            }
        }
        float a0 = 0.f, a1 = 0.f, a2 = 0.f, a3 = 0.f, a4 = 0.f;
#pragma unroll
        for (int i = 0; i < 8; i++) {
            float hv = hf[i];
            a0 += hv * pf[0][i];
            a1 += hv * pf[1][i];
            a2 += hv * pf[2][i];
            a3 += hv * pf[3][i];
            a4 += hv * pf[4][i];
        }
#pragma unroll
        for (int off = 1; off <= 4; off <<= 1) {
            a0 += __shfl_xor_sync(0xffffffffu, a0, off);
            a1 += __shfl_xor_sync(0xffffffffu, a1, off);
            a2 += __shfl_xor_sync(0xffffffffu, a2, off);
            a3 += __shfl_xor_sync(0xffffffffu, a3, off);
            a4 += __shfl_xor_sync(0xffffffffu, a4, off);
        }
        if (r < 5) {
            float v = a0;
            if (r == 1) v = a1;
            else if (r == 2) v = a2;
            else if (r == 3) v = a3;
            else if (r == 4) v = a4;
            atomicAdd(&g_aggr[(size_t)d0 * 20 + m + 4 * r], v + dval);
        }
        pos = nxt; h0v = h1v; d0 = d1;
    }
}

// ---------- k5: out = x@root_w + aggr + bias; pool by sorted batch ----------
__global__ void k5_out(const float* __restrict__ x, const float* __restrict__ rw,
                       const float* __restrict__ bias, const int* __restrict__ batch, int N) {
    __shared__ float s_rw[320];
    __shared__ float s_b[20];
    int tid = threadIdx.x;
    for (int q = tid; q < 320; q += blockDim.x) s_rw[q] = rw[q];
    if (tid < 20) s_b[tid] = bias[tid];
    __syncthreads();
    int tau = blockIdx.x * blockDim.x + tid;
    int C = (N + 19) / 20;
    if (tau >= C * 20) return;
    int c = tau / 20, o = tau % 20;
    int curg = -1;
    float acc = 0.f, cnt = 0.f;
    for (int u = 0; u < 20; u++) {
        int n = c * 20 + u;
        if (n >= N) break;
        int g = batch[n];
        float v = s_b[o] + g_aggr[(size_t)n * 20 + o];
        const float* xr = x + (size_t)n * 16;
#pragma unroll
        for (int i = 0; i < 16; i++) v += xr[i] * s_rw[i * 20 + o];
        if (g != curg) {
            if (curg >= 0) {
                atomicAdd(&g_pool[curg * 21 + o], acc);
                if (o == 0) atomicAdd(&g_pool[curg * 21 + 20], cnt);
            }
            curg = g; acc = 0.f; cnt = 0.f;
        }
        acc += v; cnt += 1.f;
    }
    if (curg >= 0) {
        atomicAdd(&g_pool[curg * 21 + o], acc);
        if (o == 0) atomicAdd(&g_pool[curg * 21 + 20], cnt);
    }
}

// ---------- k6: critic head, one block per graph ----------
__global__ void __launch_bounds__(256) k6_critic(const float* __restrict__ a,
                                                 const float* __restrict__ Wc1,
                                                 const float* __restrict__ bc1,
                                                 const float* __restrict__ Wc2,
                                                 const float* __restrict__ bc2,
                                                 float* __restrict__ out) {
    int g = blockIdx.x;
    int tid = threadIdx.x;
    __shared__ float sz[28];
    __shared__ float sp[8];
    if (tid < 28) {
        if (tid < 20) {
            float cnt = g_pool[g * 21 + 20];
            float inv = 1.f / fmaxf(cnt, 1.f);
            sz[tid] = g_pool[g * 21 + tid] * inv;
        } else {
            sz[tid] = a[g * 8 + tid - 20];
        }
    }
    __syncthreads();
    float v = bc1[tid];
#pragma unroll
    for (int i = 0; i < 28; i++) v += sz[i] * Wc1[i * 256 + tid];
    v = fmaxf(v, 0.f);
    float p = v * Wc2[tid];
#pragma unroll
    for (int off = 16; off; off >>= 1) p += __shfl_xor_sync(0xffffffffu, p, off);
    if ((tid & 31) == 0) sp[tid >> 5] = p;
    __syncthreads();
    if (tid == 0) {
        float t = 0.f;
        for (int w = 0; w < 8; w++) t += sp[w];
        out[g] = t + bc2[0];
    }
}

// ---------- launch ----------
extern "C" void kernel_launch(void* const* d_in, const int* in_sizes, int n_in,
                              void* d_out, int out_size) {
    int N = in_sizes[0] / 16;
    int E = in_sizes[1] / 16;
    int G = out_size;

    const float *x = (const float*)d_in[0];
    const float *ea = (const float*)d_in[1];
    const float *a = (const float*)d_in[2];
    const float *W1, *gamma, *beta, *W2, *b2, *rw, *bias, *Wc1, *bc1, *Wc2, *bc2;
    const int *ei, *batch;

    bool dict_order = (n_in > 4 && in_sizes[3] == 2 * E);
    if (dict_order) {
        ei    = (const int*)d_in[3];
        batch = (const int*)d_in[4];
        W1    = (const float*)d_in[5];
        gamma = (const float*)d_in[7];
        beta  = (const float*)d_in[8];
        W2    = (const float*)d_in[9];
        b2    = (const float*)d_in[10];
        rw    = (const float*)d_in[11];
        bias  = (const float*)d_in[12];
        Wc1   = (const float*)d_in[13];
        bc1   = (const float*)d_in[14];
        Wc2   = (const float*)d_in[15];
        bc2   = (const float*)d_in[16];
    } else {
        W1    = (const float*)d_in[3];
        gamma = (const float*)d_in[5];
        beta  = (const float*)d_in[6];
        W2    = (const float*)d_in[7];
        b2    = (const float*)d_in[8];
        rw    = (const float*)d_in[9];
        bias  = (const float*)d_in[10];
        Wc1   = (const float*)d_in[11];
        bc1   = (const float*)d_in[12];
        Wc2   = (const float*)d_in[13];
        bc2   = (const float*)d_in[14];
        ei    = (const int*)d_in[15];
        batch = (const int*)d_in[16];
    }

    float* out = (float*)d_out;

    k0_zero<<<1024, 256>>>(N, G);
    k1_stats<<<148, 256>>>(ea, E);
    k2_prep<<<1, 64>>>(W1, gamma, beta, 1.0f / (float)E);
    ks_hist<<<(E + 255) / 256, 256>>>(ei, E);
    ks_scan<<<1, 1024>>>(N);
    ks_scatter<<<(E + 255) / 256, 256>>>(ei, E);
    k3_P<<<592, 256>>>(x, W2, N);
    k3b_D<<<(N * 20 + 255) / 256, 256>>>(x, b2, N);
    k3c_h<<<1184, 256>>>(ea, E);
    k4_nodes<<<(N + 7) / 8, 256>>>(N);
    {
        int C = (N + 19) / 20;
        k5_out<<<(C * 20 + 255) / 256, 256>>>(x, rw, bias, batch, N);
    }
    k6_critic<<<G, 256>>>(a, Wc1, bc1, Wc2, bc2, out);
}